// round 17
// baseline (speedup 1.0000x reference)
#include <cuda_runtime.h>
#include <cuda_bf16.h>
#include <cstdint>

// LIF spiking scan:  x[B,S,H] -> spikes[B,S,H]   (B=8, S=2048, H=4096, fp32)
//   mem = decay*mem + x_t ; ref = max(ref-1,0)
//   spk = (ref==0 && mem>thr) ; mem *= (1-spk) ; ref += 5*spk
//
// Base = R16 (float4 lanes, 256x32, 6-stage cp.async, STG.128, na-encoded
// refractory): ncu 82.2us, DRAM 72.5%. R17:
//  (a) STAGES 6 -> 8: 96 outstanding cp.asyncs/thread (R15 showed 128 == the
//      LDGSTS queue cap regresses; 96 leaves headroom), chip-wide in-flight
//      8.4 -> 12.6MB. 64KB dynamic smem, 2 blocks/SM resident.
//  (b) drop __syncwarp: producer lane == consumer lane for every byte (lane l
//      copies columns l*4..l*4+3 of each row and reads exactly those), and
//      per-thread cp.async.wait_group makes a thread's own copies visible.
// na encoding: sp = (i>=na) && (mem>thr); na = sp ? i+5 : na; na -= U/chunk.

#define LIF_B 8
#define LIF_S 2048
#define LIF_H 4096

static constexpr int U = 16;               // timesteps per stage
static constexpr int STAGES = 8;           // 8*16*128*4B = 64KB dynamic smem
static constexpr int NCHUNK = LIF_S / U;   // 128
static constexpr int SMEM_BYTES = STAGES * U * 128 * 4;

__global__ __launch_bounds__(32, 2)
void lif_scan_v4na8(const float* __restrict__ x,
                    const float* __restrict__ thr_p,
                    const float* __restrict__ dec_p,
                    float* __restrict__ out)
{
    extern __shared__ float smem[];          // [STAGES][U][128]

    const int lane = threadIdx.x;            // 0..31
    const int n0   = blockIdx.x * 128;       // first neuron of this block
    const int b     = n0 >> 12;              // n0 / H
    const int hbase = n0 & (LIF_H - 1);      // n0 % H

    const float thr   = __ldg(thr_p);
    const float decay = __ldg(dec_p);

    const float* __restrict__ xbase = x   + b * (LIF_S * LIF_H) + hbase;
    float* __restrict__       obase = out + b * (LIF_S * LIF_H) + hbase + lane * 4;

    // tile row = 128 floats = 512B = one warp-wide cp.async op (16B/lane).
    // Producer lane == consumer lane for its 16B column -> no warp barrier.
    const float* __restrict__ wsrc = xbase + lane * 4;
    const unsigned smem0 =
        (unsigned)__cvta_generic_to_shared(&smem[lane * 4]);

    auto issue_chunk = [&](int c) {
        const unsigned sbase = smem0 + (unsigned)(c % STAGES) * (U * 512u);
        const float* src = wsrc + (c * U) * LIF_H;
        #pragma unroll
        for (int j = 0; j < U; ++j) {
            asm volatile("cp.async.cg.shared.global [%0], [%1], 16;\n"
                         :: "r"(sbase + (unsigned)j * 512u),
                            "l"(src + j * LIF_H));
        }
    };

    // Prologue: fill STAGES-2 stages, one commit group each.
    #pragma unroll
    for (int c = 0; c < STAGES - 2; ++c) {
        issue_chunk(c);
        asm volatile("cp.async.commit_group;\n" ::: "memory");
    }

    // 4 independent neuron states: membrane + next-eligible step (chunk-rel).
    float mem0 = 0.f, mem1 = 0.f, mem2 = 0.f, mem3 = 0.f;
    int   na0 = 0, na1 = 0, na2 = 0, na3 = 0;   // eligible when i >= na

    for (int c = 0; c < NCHUNK; ++c) {
        if (c + STAGES - 2 < NCHUNK)
            issue_chunk(c + STAGES - 2);
        // Always commit (empty tail groups keep wait_group<STAGES-2> aligned
        // so chunk c's group is guaranteed complete below).
        asm volatile("cp.async.commit_group;\n" ::: "memory");
        asm volatile("cp.async.wait_group %0;\n" :: "n"(STAGES - 2) : "memory");
        // no __syncwarp needed: each thread reads only its own cp.async data

        const int s = c % STAGES;

        float4 v[U];
        #pragma unroll
        for (int i = 0; i < U; ++i)
            v[i] = *reinterpret_cast<const float4*>(&smem[s * (U * 128) + i * 128 + lane * 4]);

        float* __restrict__ o = obase + (c * U) * LIF_H;
        #pragma unroll
        for (int i = 0; i < U; ++i) {
            float4 spk;

            mem0 = fmaf(decay, mem0, v[i].x);
            {
                const bool sp = (i >= na0) & (mem0 > thr);
                spk.x = sp ? 1.0f : 0.0f;
                mem0  = sp ? 0.0f : mem0;
                na0   = sp ? (i + 5) : na0;
            }
            mem1 = fmaf(decay, mem1, v[i].y);
            {
                const bool sp = (i >= na1) & (mem1 > thr);
                spk.y = sp ? 1.0f : 0.0f;
                mem1  = sp ? 0.0f : mem1;
                na1   = sp ? (i + 5) : na1;
            }
            mem2 = fmaf(decay, mem2, v[i].z);
            {
                const bool sp = (i >= na2) & (mem2 > thr);
                spk.z = sp ? 1.0f : 0.0f;
                mem2  = sp ? 0.0f : mem2;
                na2   = sp ? (i + 5) : na2;
            }
            mem3 = fmaf(decay, mem3, v[i].w);
            {
                const bool sp = (i >= na3) & (mem3 > thr);
                spk.w = sp ? 1.0f : 0.0f;
                mem3  = sp ? 0.0f : mem3;
                na3   = sp ? (i + 5) : na3;
            }

            *reinterpret_cast<float4*>(&o[i * LIF_H]) = spk;   // STG.128
        }

        // Shift next-eligible times into the next chunk's local frame.
        na0 -= U; na1 -= U; na2 -= U; na3 -= U;
    }
}

extern "C" void kernel_launch(void* const* d_in, const int* in_sizes, int n_in,
                              void* d_out, int out_size)
{
    // metadata order: x [B,S,H] f32, membrane_threshold f32, decay_rate f32
    const float* x     = (const float*)d_in[0];
    const float* thr_p = (const float*)d_in[1];
    const float* dec_p = (const float*)d_in[2];
    float* out = (float*)d_out;

    cudaFuncSetAttribute(lif_scan_v4na8,
                         cudaFuncAttributeMaxDynamicSharedMemorySize, SMEM_BYTES);

    const int blocks = (LIF_B * LIF_H) / 128;   // 256 blocks, exact cover

    lif_scan_v4na8<<<blocks, 32, SMEM_BYTES>>>(x, thr_p, dec_p, out);
}